// round 4
// baseline (speedup 1.0000x reference)
#include <cuda_runtime.h>
#include <stdint.h>

// ---------------------------------------------------------------------------
// ExpertBuffer fetch_on_demand — block-chunked fused copy.
// out = concat(w13_cache', w13_bias_cache', w2_cache', w2_bias_cache'),
// cache'[s] = src[e] if slot s was scattered (last pair wins) else cache[s].
//
// Each block owns one contiguous CHUNK4 (8192 float4 = 128KB) of out.
// Region/slot/base resolved once per block; inner loop is a pure streaming
// copy. Chunks crossing slot/region boundaries (bias regions) fall back to a
// per-element path — ~2 of ~1538 blocks.
// ---------------------------------------------------------------------------

#define MAX_SLOTS 1024
#define CHUNK4    8192u      // float4 per block (128 KB)
#define THREADS   256
#define UNROLL    8

struct Region {
    const float4* src;
    const float4* cache;
    unsigned base;   // prefix offset in out (float4 units)
    unsigned limit;  // end offset in out (float4 units)
    unsigned per4;   // float4 per slot
    int shift;       // log2(per4) if pow2, else -1
};

__device__ __forceinline__ const Region* pick_region(
    unsigned i, const Region* r)
{
    if (i < r[1].base) return &r[0];
    if (i < r[2].base) return &r[1];
    if (i < r[3].base) return &r[2];
    return &r[3];
}

__device__ __forceinline__ const float4* slot_base(
    const Region* r, unsigned s, const int* smap)
{
    int e = smap[s];
    return (e >= 0) ? (r->src + (size_t)(unsigned)e * r->per4)
                    : (r->cache + (size_t)s * r->per4);
}

__global__ void __launch_bounds__(THREADS, 8)
chunked_gather_copy(
    const float4* __restrict__ w13_src,  const float4* __restrict__ w13_cache,
    const float4* __restrict__ b13_src,  const float4* __restrict__ b13_cache,
    const float4* __restrict__ w2_src,   const float4* __restrict__ w2_cache,
    const float4* __restrict__ b2_src,   const float4* __restrict__ b2_cache,
    float4* __restrict__ out,
    const int* __restrict__ expert_ids, const int* __restrict__ slot_ids,
    int n_pairs, int n_slots,
    unsigned off1, unsigned off2, unsigned off3, unsigned total,
    unsigned per13, int sh13, unsigned perb13, int shb13,
    unsigned per2,  int sh2,  unsigned perb2,  int shb2)
{
    __shared__ int smap[MAX_SLOTS];

    for (int s = threadIdx.x; s < n_slots; s += blockDim.x) {
        int e = -1;
        for (int i = 0; i < n_pairs; ++i)
            if (slot_ids[i] == s) e = expert_ids[i];
        smap[s] = e;
    }
    __syncthreads();

    Region regs[4] = {
        { w13_src, w13_cache, 0u,   off1,  per13,  sh13  },
        { b13_src, b13_cache, off1, off2,  perb13, shb13 },
        { w2_src,  w2_cache,  off2, off3,  per2,   sh2   },
        { b2_src,  b2_cache,  off3, total, perb2,  shb2  },
    };

    unsigned chunk_start = blockIdx.x * CHUNK4;
    if (chunk_start >= total) return;

    const Region* r = pick_region(chunk_start, regs);
    unsigned local = chunk_start - r->base;

    // Fast path: full chunk entirely inside one slot of one region.
    bool fast = false;
    unsigned s = 0, off = 0;
    if (chunk_start + CHUNK4 <= r->limit) {
        if (r->shift >= 0) {
            s   = local >> r->shift;
            off = local & (r->per4 - 1u);
        } else {
            s   = local / r->per4;
            off = local - s * r->per4;
        }
        fast = (off + CHUNK4 <= r->per4);
    }

    if (fast) {
        const float4* __restrict__ src = slot_base(r, s, smap) + off;
        float4* __restrict__ dst = out + chunk_start;
        // 8192 f4 / 256 threads = 32 f4/thread; 4 outer iters of 8-deep MLP.
        #pragma unroll
        for (unsigned k = 0; k < CHUNK4 / (THREADS * UNROLL); ++k) {
            unsigned j = threadIdx.x + k * (THREADS * UNROLL);
            float4 v[UNROLL];
            #pragma unroll
            for (int u = 0; u < UNROLL; ++u)
                v[u] = __ldcs(src + j + (unsigned)u * THREADS);
            #pragma unroll
            for (int u = 0; u < UNROLL; ++u)
                __stcs(dst + j + (unsigned)u * THREADS, v[u]);
        }
    } else {
        // Slow path: per-element with full dispatch (bias chunks only).
        unsigned end = chunk_start + CHUNK4;
        if (end > total) end = total;
        for (unsigned i = chunk_start + threadIdx.x; i < end; i += THREADS) {
            const Region* q = pick_region(i, regs);
            unsigned l = i - q->base;
            unsigned qs, qo;
            if (q->shift >= 0) {
                qs = l >> q->shift;
                qo = l & (q->per4 - 1u);
            } else {
                qs = l / q->per4;
                qo = l - qs * q->per4;
            }
            __stcs(out + i, __ldcs(slot_base(q, qs, smap) + qo));
        }
    }
}

static inline int ilog2_if_pow2(long v) {
    if (v > 0 && (v & (v - 1)) == 0) {
        int s = 0;
        while ((1L << s) < v) ++s;
        return s;
    }
    return -1;
}

extern "C" void kernel_launch(void* const* d_in, const int* in_sizes, int n_in,
                              void* d_out, int out_size) {
    const float* w13_src    = (const float*)d_in[0];
    const float* b13_src    = (const float*)d_in[1];
    const float* w2_src     = (const float*)d_in[2];
    const float* b2_src     = (const float*)d_in[3];
    const float* w13_cache  = (const float*)d_in[4];
    const float* b13_cache  = (const float*)d_in[5];
    const float* w2_cache   = (const float*)d_in[6];
    const float* b2_cache   = (const float*)d_in[7];
    const int*   expert_ids = (const int*)d_in[8];
    const int*   slot_ids   = (const int*)d_in[9];

    int n_pairs = in_sizes[8];
    int n_slots = in_sizes[9];

    long n13  = in_sizes[4];
    long nb13 = in_sizes[5];
    long n2   = in_sizes[6];
    long nb2  = in_sizes[7];

    unsigned per13  = (unsigned)((n13  / n_slots) >> 2);
    unsigned perb13 = (unsigned)((nb13 / n_slots) >> 2);
    unsigned per2   = (unsigned)((n2   / n_slots) >> 2);
    unsigned perb2  = (unsigned)((nb2  / n_slots) >> 2);

    unsigned off1 = (unsigned)(n13 >> 2);
    unsigned off2 = off1 + (unsigned)(nb13 >> 2);
    unsigned off3 = off2 + (unsigned)(n2 >> 2);
    unsigned total = off3 + (unsigned)(nb2 >> 2);

    int sh13  = ilog2_if_pow2(per13);
    int shb13 = ilog2_if_pow2(perb13);
    int sh2   = ilog2_if_pow2(per2);
    int shb2  = ilog2_if_pow2(perb2);

    unsigned blocks = (total + CHUNK4 - 1) / CHUNK4;

    chunked_gather_copy<<<blocks, THREADS>>>(
        (const float4*)w13_src, (const float4*)w13_cache,
        (const float4*)b13_src, (const float4*)b13_cache,
        (const float4*)w2_src,  (const float4*)w2_cache,
        (const float4*)b2_src,  (const float4*)b2_cache,
        (float4*)d_out,
        expert_ids, slot_ids, n_pairs, n_slots,
        off1, off2, off3, total,
        per13, sh13, perb13, shb13,
        per2, sh2, perb2, shb2);
}

// round 5
// speedup vs baseline: 1.1557x; 1.1557x over previous
#include <cuda_runtime.h>
#include <stdint.h>

// ---------------------------------------------------------------------------
// ExpertBuffer fetch_on_demand — fused grid-stride copy with streaming ld/st.
// out = concat(w13_cache', w13_bias_cache', w2_cache', w2_bias_cache'),
// cache'[s] = src[e] if slot s scattered (last pair wins) else cache[s].
//
// R5 = R2 structure (UNROLL=4, low regs, high occ) + R3 streaming hints
// (reduced DRAM traffic) + exactly one resident wave.
// ---------------------------------------------------------------------------

#define MAX_SLOTS 1024
#define THREADS   256
#define UNROLL    4

struct Region {
    const float4* src;
    const float4* cache;
    unsigned base;   // prefix offset of this region in out (float4 units)
    unsigned per4;   // float4s per expert/slot in this region
    int shift;       // log2(per4) if pow2, else -1
};

__device__ __forceinline__ float4 fetch_one(
    unsigned i,
    const Region& r0, const Region& r1, const Region& r2, const Region& r3,
    unsigned off1, unsigned off2, unsigned off3,
    const int* __restrict__ smap)
{
    const Region* r;
    if (i < off1)      r = &r0;
    else if (i < off2) r = &r1;
    else if (i < off3) r = &r2;
    else               r = &r3;

    unsigned local = i - r->base;
    unsigned s, off;
    if (r->shift >= 0) {
        s   = local >> r->shift;
        off = local & (r->per4 - 1u);
    } else {
        s   = local / r->per4;
        off = local - s * r->per4;
    }
    int e = smap[s];
    const float4* p = (e >= 0) ? (r->src + (size_t)(unsigned)e * r->per4)
                               : (r->cache + (size_t)s * r->per4);
    return __ldcs(p + off);   // streaming: no reuse, don't pollute L2
}

__global__ void __launch_bounds__(THREADS, 8)
fused_gather_copy(
    const float4* __restrict__ w13_src,  const float4* __restrict__ w13_cache,
    const float4* __restrict__ b13_src,  const float4* __restrict__ b13_cache,
    const float4* __restrict__ w2_src,   const float4* __restrict__ w2_cache,
    const float4* __restrict__ b2_src,   const float4* __restrict__ b2_cache,
    float4* __restrict__ out,
    const int* __restrict__ expert_ids, const int* __restrict__ slot_ids,
    int n_pairs, int n_slots,
    unsigned off1, unsigned off2, unsigned off3, unsigned total,
    unsigned per13, int sh13, unsigned perb13, int shb13,
    unsigned per2,  int sh2,  unsigned perb2,  int shb2)
{
    __shared__ int smap[MAX_SLOTS];

    for (int s = threadIdx.x; s < n_slots; s += blockDim.x) {
        int e = -1;
        for (int i = 0; i < n_pairs; ++i)
            if (slot_ids[i] == s) e = expert_ids[i];
        smap[s] = e;
    }
    __syncthreads();

    Region r0 = { w13_src, w13_cache, 0u,   per13,  sh13  };
    Region r1 = { b13_src, b13_cache, off1, perb13, shb13 };
    Region r2 = { w2_src,  w2_cache,  off2, per2,   sh2   };
    Region r3 = { b2_src,  b2_cache,  off3, perb2,  shb2  };

    const unsigned stride = blockDim.x * gridDim.x;
    unsigned i = blockIdx.x * blockDim.x + threadIdx.x;

    // UNROLL independent LDG.128 in flight before the store burst.
    for (; i + (UNROLL - 1u) * stride < total; i += (unsigned)UNROLL * stride) {
        float4 v[UNROLL];
        #pragma unroll
        for (int u = 0; u < UNROLL; ++u)
            v[u] = fetch_one(i + (unsigned)u * stride,
                             r0, r1, r2, r3, off1, off2, off3, smap);
        #pragma unroll
        for (int u = 0; u < UNROLL; ++u)
            __stcs(out + i + (unsigned)u * stride, v[u]);
    }
    for (; i < total; i += stride)
        __stcs(out + i, fetch_one(i, r0, r1, r2, r3, off1, off2, off3, smap));
}

static inline int ilog2_if_pow2(long v) {
    if (v > 0 && (v & (v - 1)) == 0) {
        int s = 0;
        while ((1L << s) < v) ++s;
        return s;
    }
    return -1;
}

extern "C" void kernel_launch(void* const* d_in, const int* in_sizes, int n_in,
                              void* d_out, int out_size) {
    const float* w13_src    = (const float*)d_in[0];
    const float* b13_src    = (const float*)d_in[1];
    const float* w2_src     = (const float*)d_in[2];
    const float* b2_src     = (const float*)d_in[3];
    const float* w13_cache  = (const float*)d_in[4];
    const float* b13_cache  = (const float*)d_in[5];
    const float* w2_cache   = (const float*)d_in[6];
    const float* b2_cache   = (const float*)d_in[7];
    const int*   expert_ids = (const int*)d_in[8];
    const int*   slot_ids   = (const int*)d_in[9];

    int n_pairs = in_sizes[8];
    int n_slots = in_sizes[9];

    long n13  = in_sizes[4];
    long nb13 = in_sizes[5];
    long n2   = in_sizes[6];
    long nb2  = in_sizes[7];

    unsigned per13  = (unsigned)((n13  / n_slots) >> 2);
    unsigned perb13 = (unsigned)((nb13 / n_slots) >> 2);
    unsigned per2   = (unsigned)((n2   / n_slots) >> 2);
    unsigned perb2  = (unsigned)((nb2  / n_slots) >> 2);

    unsigned off1 = (unsigned)(n13 >> 2);
    unsigned off2 = off1 + (unsigned)(nb13 >> 2);
    unsigned off3 = off2 + (unsigned)(n2 >> 2);
    unsigned total = off3 + (unsigned)(nb2 >> 2);

    int sh13  = ilog2_if_pow2(per13);
    int shb13 = ilog2_if_pow2(perb13);
    int sh2   = ilog2_if_pow2(per2);
    int shb2  = ilog2_if_pow2(perb2);

    // Exactly one resident wave: 148 SMs * 8 blocks * 256 threads.
    int threads = THREADS;
    int blocks  = 148 * 8;
    unsigned max_blocks = (total + threads - 1) / threads;
    if ((unsigned)blocks > max_blocks) blocks = (int)max_blocks;

    fused_gather_copy<<<blocks, threads>>>(
        (const float4*)w13_src, (const float4*)w13_cache,
        (const float4*)b13_src, (const float4*)b13_cache,
        (const float4*)w2_src,  (const float4*)w2_cache,
        (const float4*)b2_src,  (const float4*)b2_cache,
        (float4*)d_out,
        expert_ids, slot_ids, n_pairs, n_slots,
        off1, off2, off3, total,
        per13, sh13, perb13, shb13,
        per2, sh2, perb2, shb2);
}

// round 6
// speedup vs baseline: 1.2366x; 1.0700x over previous
#include <cuda_runtime.h>
#include <stdint.h>

// ---------------------------------------------------------------------------
// ExpertBuffer fetch_on_demand — TMA bulk-copy pipeline.
//
// out = concat(w13_cache', w13_bias_cache', w2_cache', w2_bias_cache'),
// cache'[s] = src[e] if slot s scattered (last pair wins) else cache[s].
//
// The output is carved into 16KB pieces. Every region whose per-slot byte
// size is 16KB-divisible is copied via cp.async.bulk (TMA engine):
//   gmem --bulk G2S--> smem buf --bulk S2G--> gmem
// 3-buffer pipeline per block, lookahead-2 loads, driven by thread 0.
// Regions not 16KB-divisible (w2_bias: 4KB/slot) use an elementwise
// streaming fallback executed cooperatively by all threads first.
// ---------------------------------------------------------------------------

#define PIECE     16384u
#define NBUF      3
#define TPB       32
#define MAX_SLOTS 1024

// dynamic smem layout (bytes)
#define SM_SMAP   0                       // int[MAX_SLOTS] = 4096 B
#define SM_MBAR   4096                    // 3 * 8 B
#define SM_BUF    4224                    // 128-aligned buffers
#define SM_TOTAL  (SM_BUF + NBUF * PIECE) // 53376 B

// ---- PTX helpers -----------------------------------------------------------
__device__ __forceinline__ uint32_t smem_u32(const void* p) {
    uint32_t a;
    asm("{ .reg .u64 t; cvta.to.shared.u64 t, %1; cvt.u32.u64 %0, t; }"
        : "=r"(a) : "l"(p));
    return a;
}

#define MBARRIER_INIT(addr, cnt) \
    asm volatile("mbarrier.init.shared.b64 [%0], %1;" \
                 :: "r"(addr), "r"(cnt) : "memory")

#define MBARRIER_EXPECT_TX(addr, bytes) \
    asm volatile("mbarrier.arrive.expect_tx.shared.b64 _, [%0], %1;" \
                 :: "r"(addr), "r"(bytes) : "memory")

#define MBARRIER_WAIT_PARITY(addr, parity) do {                              \
    uint32_t _m = (addr); uint32_t _p = (parity); uint32_t _d;               \
    asm volatile("{\n\t.reg .pred p;\n\t"                                    \
        "mbarrier.try_wait.parity.acquire.cta.shared::cta.b64 p, [%1], %2;\n\t" \
        "selp.b32 %0, 1, 0, p;\n\t}"                                         \
        : "=r"(_d) : "r"(_m), "r"(_p) : "memory");                           \
    if (!_d) {                                                               \
        asm volatile("{\n\t.reg .pred P1;\n\t"                               \
            "W_%=:\n\t"                                                      \
            "mbarrier.try_wait.parity.acquire.cta.shared::cta.b64 P1, [%0], %1, 0x989680;\n\t" \
            "@P1 bra.uni D_%=;\n\t"                                          \
            "bra.uni W_%=;\n\t"                                              \
            "D_%=:\n\t}"                                                     \
            :: "r"(_m), "r"(_p) : "memory");                                 \
    }                                                                        \
} while (0)

#define BULK_LOAD(smem_addr, gptr, bytes, mbar_addr) \
    asm volatile("cp.async.bulk.shared::cta.global.mbarrier::complete_tx::bytes " \
                 "[%0], [%1], %2, [%3];" \
                 :: "r"(smem_addr), "l"(gptr), "r"(bytes), "r"(mbar_addr) : "memory")

#define BULK_STORE(gptr, smem_addr, bytes) \
    asm volatile("cp.async.bulk.global.shared::cta.bulk_group [%0], [%1], %2;" \
                 :: "l"(gptr), "r"(smem_addr), "r"(bytes) : "memory")

#define BULK_COMMIT() asm volatile("cp.async.bulk.commit_group;" ::: "memory")

template <int N>
__device__ __forceinline__ void bulk_wait_group() {
    asm volatile("cp.async.bulk.wait_group %0;" :: "n"(N) : "memory");
}

// ---- region meta ------------------------------------------------------------
struct RMeta {
    const char* src;
    const char* cache;
    size_t   base;   // byte offset of region in out
    unsigned per;    // bytes per slot
    unsigned pps;    // 16KB pieces per slot (0 => fallback region)
    unsigned end;    // cumulative piece-count prefix end
};

__global__ void __launch_bounds__(TPB)
tma_gather_copy(
    const char* s0, const char* c0, const char* s1, const char* c1,
    const char* s2, const char* c2, const char* s3, const char* c3,
    char* __restrict__ out,
    const int* __restrict__ expert_ids, const int* __restrict__ slot_ids,
    int n_pairs, int n_slots,
    unsigned per0, unsigned per1, unsigned per2, unsigned per3,
    unsigned pps0, unsigned pps1, unsigned pps2, unsigned pps3,
    unsigned end0, unsigned end1, unsigned end2, unsigned end3,
    unsigned long base0, unsigned long base1, unsigned long base2, unsigned long base3)
{
    extern __shared__ char sm[];
    int* smap = (int*)(sm + SM_SMAP);
    const uint32_t smb = smem_u32(sm);
    const int tid = threadIdx.x;

    // slot -> expert map (last pair wins)
    for (int s = tid; s < n_slots; s += TPB) {
        int e = -1;
        for (int i = 0; i < n_pairs; ++i)
            if (slot_ids[i] == s) e = expert_ids[i];
        smap[s] = e;
    }
    if (tid == 0) {
        #pragma unroll
        for (int b = 0; b < NBUF; ++b)
            MBARRIER_INIT(smb + SM_MBAR + 8u * b, 1);
    }
    __syncthreads();

    RMeta rm[4] = {
        { s0, c0, (size_t)base0, per0, pps0, end0 },
        { s1, c1, (size_t)base1, per1, pps1, end1 },
        { s2, c2, (size_t)base2, per2, pps2, end2 },
        { s3, c3, (size_t)base3, per3, pps3, end3 },
    };

    // ---- fallback: regions whose per-slot size isn't 16KB-divisible --------
    // elementwise streaming copy, all threads of all blocks, grid-stride.
    {
        const unsigned gstride = gridDim.x * TPB;
        const unsigned gtid = blockIdx.x * TPB + tid;
        #pragma unroll
        for (int r = 0; r < 4; ++r) {
            if (rm[r].pps != 0 || rm[r].per == 0) continue;
            unsigned per4 = rm[r].per >> 4;              // float4 per slot
            unsigned tot4 = per4 * (unsigned)n_slots;
            float4* dst = (float4*)(out + rm[r].base);
            for (unsigned i = gtid; i < tot4; i += gstride) {
                unsigned s  = i / per4;
                unsigned o  = i - s * per4;
                int e = smap[s];
                const float4* p = (e >= 0)
                    ? (const float4*)(rm[r].src  + (size_t)(unsigned)e * rm[r].per) + o
                    : (const float4*)(rm[r].cache + (size_t)s * rm[r].per) + o;
                __stcs(dst + i, __ldcs(p));
            }
        }
    }

    // ---- TMA bulk pipeline (thread 0 only) ----------------------------------
    if (tid != 0) return;

    const unsigned n_pieces = end3;
    const unsigned bid = blockIdx.x, grid = gridDim.x;
    const unsigned n_my = (n_pieces > bid)
                        ? (n_pieces - bid + grid - 1) / grid : 0;
    if (n_my == 0) return;

    auto resolve = [&](unsigned k, const char** sg, char** dg) {
        unsigned p = bid + k * grid;        // global piece id
        int r = 0; unsigned prev = 0;
        while (p >= rm[r].end) { prev = rm[r].end; ++r; }
        unsigned lp = p - prev;
        unsigned s  = lp / rm[r].pps;
        unsigned po = lp - s * rm[r].pps;
        int e = smap[s];
        const char* b = (e >= 0)
            ? rm[r].src  + (size_t)(unsigned)e * rm[r].per
            : rm[r].cache + (size_t)s * rm[r].per;
        *sg = b + (size_t)po * PIECE;
        *dg = out + rm[r].base + (size_t)lp * PIECE;
    };

    auto issue_load = [&](unsigned k) {
        const char* sg; char* dg;
        resolve(k, &sg, &dg);
        unsigned b = k % NBUF;
        uint32_t mb = smb + SM_MBAR + 8u * b;
        MBARRIER_EXPECT_TX(mb, PIECE);
        BULK_LOAD(smb + SM_BUF + b * PIECE, sg, PIECE, mb);
    };

    int ph[NBUF] = {0, 0, 0};

    // prologue: 2 loads in flight
    issue_load(0);
    if (n_my > 1) issue_load(1);

    for (unsigned k = 0; k < n_my; ++k) {
        unsigned b = k % NBUF;
        MBARRIER_WAIT_PARITY(smb + SM_MBAR + 8u * b, ph[b]);
        ph[b] ^= 1;

        const char* sg; char* dg;
        resolve(k, &sg, &dg);
        BULK_STORE(dg, smb + SM_BUF + b * PIECE, PIECE);
        BULK_COMMIT();

        // ensure the buffer the k+2 load targets has finished its old store
        bulk_wait_group<1>();
        if (k + 2 < n_my) issue_load(k + 2);
    }
    bulk_wait_group<0>();
}

extern "C" void kernel_launch(void* const* d_in, const int* in_sizes, int n_in,
                              void* d_out, int out_size) {
    const char* s[4]  = { (const char*)d_in[0], (const char*)d_in[1],
                          (const char*)d_in[2], (const char*)d_in[3] };
    const char* c[4]  = { (const char*)d_in[4], (const char*)d_in[5],
                          (const char*)d_in[6], (const char*)d_in[7] };
    const int* expert_ids = (const int*)d_in[8];
    const int* slot_ids   = (const int*)d_in[9];

    int n_pairs = in_sizes[8];
    int n_slots = in_sizes[9];

    unsigned per[4], pps[4], end[4];
    unsigned long base[4];
    unsigned long off = 0;
    unsigned cum = 0;
    for (int r = 0; r < 4; ++r) {
        unsigned long region_bytes = (unsigned long)in_sizes[4 + r] * 4ul;
        per[r]  = (unsigned)(region_bytes / (unsigned long)n_slots);
        pps[r]  = (per[r] % PIECE == 0) ? per[r] / PIECE : 0u;
        cum    += pps[r] * (unsigned)n_slots;
        end[r]  = cum;
        base[r] = off;
        off    += region_bytes;
    }

    static bool attr_done = false;
    if (!attr_done) {
        cudaFuncSetAttribute(tma_gather_copy,
                             cudaFuncAttributeMaxDynamicSharedMemorySize,
                             SM_TOTAL);
        attr_done = true;
    }

    int blocks = 152 * 4;   // 4 blocks/SM (smem-limited), one wave
    tma_gather_copy<<<blocks, TPB, SM_TOTAL>>>(
        s[0], c[0], s[1], c[1], s[2], c[2], s[3], c[3],
        (char*)d_out, expert_ids, slot_ids, n_pairs, n_slots,
        per[0], per[1], per[2], per[3],
        pps[0], pps[1], pps[2], pps[3],
        end[0], end[1], end[2], end[3],
        base[0], base[1], base[2], base[3]);
}

// round 7
// speedup vs baseline: 1.2564x; 1.0160x over previous
#include <cuda_runtime.h>
#include <stdint.h>

// ---------------------------------------------------------------------------
// ExpertBuffer fetch_on_demand — TMA bulk-copy pipeline, 32KB pieces.
//
// out = concat(w13_cache', w13_bias_cache', w2_cache', w2_bias_cache'),
// cache'[s] = src[e] if slot s scattered (last pair wins) else cache[s].
//
// Output carved into 32KB pieces; regions whose per-slot size divides 32KB
// (w13: 16MB/slot, w2: 8MB/slot) stream through cp.async.bulk G2S + S2G with
// a 3-buffer pipeline per block (lookahead-2 loads). Bias regions (16KB and
// 4KB per slot) are copied elementwise up front — 160KB total, noise.
// ---------------------------------------------------------------------------

#define PIECE     32768u
#define NBUF      3
#define TPB       32
#define MAX_SLOTS 1024

// dynamic smem layout (bytes)
#define SM_SMAP   0                       // int[MAX_SLOTS] = 4096 B
#define SM_MBAR   4096                    // NBUF * 8 B
#define SM_BUF    4224                    // 128-aligned buffers
#define SM_TOTAL  (SM_BUF + NBUF * PIECE) // 102528 B -> 2 blocks/SM

// ---- PTX helpers -----------------------------------------------------------
__device__ __forceinline__ uint32_t smem_u32(const void* p) {
    uint32_t a;
    asm("{ .reg .u64 t; cvta.to.shared.u64 t, %1; cvt.u32.u64 %0, t; }"
        : "=r"(a) : "l"(p));
    return a;
}

#define MBARRIER_INIT(addr, cnt) \
    asm volatile("mbarrier.init.shared.b64 [%0], %1;" \
                 :: "r"(addr), "r"(cnt) : "memory")

#define MBARRIER_EXPECT_TX(addr, bytes) \
    asm volatile("mbarrier.arrive.expect_tx.shared.b64 _, [%0], %1;" \
                 :: "r"(addr), "r"(bytes) : "memory")

#define MBARRIER_WAIT_PARITY(addr, parity) do {                              \
    uint32_t _m = (addr); uint32_t _p = (parity); uint32_t _d;               \
    asm volatile("{\n\t.reg .pred p;\n\t"                                    \
        "mbarrier.try_wait.parity.acquire.cta.shared::cta.b64 p, [%1], %2;\n\t" \
        "selp.b32 %0, 1, 0, p;\n\t}"                                         \
        : "=r"(_d) : "r"(_m), "r"(_p) : "memory");                           \
    if (!_d) {                                                               \
        asm volatile("{\n\t.reg .pred P1;\n\t"                               \
            "W_%=:\n\t"                                                      \
            "mbarrier.try_wait.parity.acquire.cta.shared::cta.b64 P1, [%0], %1, 0x989680;\n\t" \
            "@P1 bra.uni D_%=;\n\t"                                          \
            "bra.uni W_%=;\n\t"                                              \
            "D_%=:\n\t}"                                                     \
            :: "r"(_m), "r"(_p) : "memory");                                 \
    }                                                                        \
} while (0)

#define BULK_LOAD(smem_addr, gptr, bytes, mbar_addr) \
    asm volatile("cp.async.bulk.shared::cta.global.mbarrier::complete_tx::bytes " \
                 "[%0], [%1], %2, [%3];" \
                 :: "r"(smem_addr), "l"(gptr), "r"(bytes), "r"(mbar_addr) : "memory")

#define BULK_STORE(gptr, smem_addr, bytes) \
    asm volatile("cp.async.bulk.global.shared::cta.bulk_group [%0], [%1], %2;" \
                 :: "l"(gptr), "r"(smem_addr), "r"(bytes) : "memory")

#define BULK_COMMIT() asm volatile("cp.async.bulk.commit_group;" ::: "memory")

template <int N>
__device__ __forceinline__ void bulk_wait_group() {
    asm volatile("cp.async.bulk.wait_group %0;" :: "n"(N) : "memory");
}

// ---- region meta ------------------------------------------------------------
struct RMeta {
    const char* src;
    const char* cache;
    size_t   base;   // byte offset of region in out
    unsigned per;    // bytes per slot
    unsigned pps;    // PIECE-sized pieces per slot (0 => fallback region)
    unsigned end;    // cumulative piece-count prefix end
};

__global__ void __launch_bounds__(TPB)
tma_gather_copy(
    const char* s0, const char* c0, const char* s1, const char* c1,
    const char* s2, const char* c2, const char* s3, const char* c3,
    char* __restrict__ out,
    const int* __restrict__ expert_ids, const int* __restrict__ slot_ids,
    int n_pairs, int n_slots,
    unsigned per0, unsigned per1, unsigned per2, unsigned per3,
    unsigned pps0, unsigned pps1, unsigned pps2, unsigned pps3,
    unsigned end0, unsigned end1, unsigned end2, unsigned end3,
    unsigned long base0, unsigned long base1, unsigned long base2, unsigned long base3)
{
    extern __shared__ char sm[];
    int* smap = (int*)(sm + SM_SMAP);
    const uint32_t smb = smem_u32(sm);
    const int tid = threadIdx.x;

    // slot -> expert map (last pair wins)
    for (int s = tid; s < n_slots; s += TPB) {
        int e = -1;
        for (int i = 0; i < n_pairs; ++i)
            if (slot_ids[i] == s) e = expert_ids[i];
        smap[s] = e;
    }
    if (tid == 0) {
        #pragma unroll
        for (int b = 0; b < NBUF; ++b)
            MBARRIER_INIT(smb + SM_MBAR + 8u * b, 1);
    }
    __syncthreads();

    RMeta rm[4] = {
        { s0, c0, (size_t)base0, per0, pps0, end0 },
        { s1, c1, (size_t)base1, per1, pps1, end1 },
        { s2, c2, (size_t)base2, per2, pps2, end2 },
        { s3, c3, (size_t)base3, per3, pps3, end3 },
    };

    // ---- fallback: regions whose per-slot size isn't PIECE-divisible -------
    // elementwise streaming copy, all threads of all blocks, grid-stride.
    {
        const unsigned gstride = gridDim.x * TPB;
        const unsigned gtid = blockIdx.x * TPB + tid;
        #pragma unroll
        for (int r = 0; r < 4; ++r) {
            if (rm[r].pps != 0 || rm[r].per == 0) continue;
            unsigned per4 = rm[r].per >> 4;              // float4 per slot
            unsigned tot4 = per4 * (unsigned)n_slots;
            float4* dst = (float4*)(out + rm[r].base);
            for (unsigned i = gtid; i < tot4; i += gstride) {
                unsigned s  = i / per4;
                unsigned o  = i - s * per4;
                int e = smap[s];
                const float4* p = (e >= 0)
                    ? (const float4*)(rm[r].src  + (size_t)(unsigned)e * rm[r].per) + o
                    : (const float4*)(rm[r].cache + (size_t)s * rm[r].per) + o;
                __stcs(dst + i, __ldcs(p));
            }
        }
    }

    // ---- TMA bulk pipeline (thread 0 only) ----------------------------------
    if (tid != 0) return;

    const unsigned n_pieces = end3;
    const unsigned bid = blockIdx.x, grid = gridDim.x;
    const unsigned n_my = (n_pieces > bid)
                        ? (n_pieces - bid + grid - 1) / grid : 0;
    if (n_my == 0) return;

    auto resolve = [&](unsigned k, const char** sg, char** dg) {
        unsigned p = bid + k * grid;        // global piece id
        int r = 0; unsigned prev = 0;
        while (p >= rm[r].end) { prev = rm[r].end; ++r; }
        unsigned lp = p - prev;
        unsigned s  = lp / rm[r].pps;
        unsigned po = lp - s * rm[r].pps;
        int e = smap[s];
        const char* b = (e >= 0)
            ? rm[r].src  + (size_t)(unsigned)e * rm[r].per
            : rm[r].cache + (size_t)s * rm[r].per;
        *sg = b + (size_t)po * PIECE;
        *dg = out + rm[r].base + (size_t)lp * PIECE;
    };

    auto issue_load = [&](unsigned k) {
        const char* sg; char* dg;
        resolve(k, &sg, &dg);
        unsigned b = k % NBUF;
        uint32_t mb = smb + SM_MBAR + 8u * b;
        MBARRIER_EXPECT_TX(mb, PIECE);
        BULK_LOAD(smb + SM_BUF + b * PIECE, sg, PIECE, mb);
    };

    int ph[NBUF] = {0, 0, 0};

    // prologue: 2 loads in flight
    issue_load(0);
    if (n_my > 1) issue_load(1);

    for (unsigned k = 0; k < n_my; ++k) {
        unsigned b = k % NBUF;
        MBARRIER_WAIT_PARITY(smb + SM_MBAR + 8u * b, ph[b]);
        ph[b] ^= 1;

        const char* sg; char* dg;
        resolve(k, &sg, &dg);
        BULK_STORE(dg, smb + SM_BUF + b * PIECE, PIECE);
        BULK_COMMIT();

        // buffer targeted by load k+2 must have its old store (group k-1) done
        bulk_wait_group<1>();
        if (k + 2 < n_my) issue_load(k + 2);
    }
    bulk_wait_group<0>();
}

extern "C" void kernel_launch(void* const* d_in, const int* in_sizes, int n_in,
                              void* d_out, int out_size) {
    const char* s[4]  = { (const char*)d_in[0], (const char*)d_in[1],
                          (const char*)d_in[2], (const char*)d_in[3] };
    const char* c[4]  = { (const char*)d_in[4], (const char*)d_in[5],
                          (const char*)d_in[6], (const char*)d_in[7] };
    const int* expert_ids = (const int*)d_in[8];
    const int* slot_ids   = (const int*)d_in[9];

    int n_pairs = in_sizes[8];
    int n_slots = in_sizes[9];

    unsigned per[4], pps[4], end[4];
    unsigned long base[4];
    unsigned long off = 0;
    unsigned cum = 0;
    for (int r = 0; r < 4; ++r) {
        unsigned long region_bytes = (unsigned long)in_sizes[4 + r] * 4ul;
        per[r]  = (unsigned)(region_bytes / (unsigned long)n_slots);
        pps[r]  = (per[r] % PIECE == 0) ? per[r] / PIECE : 0u;
        cum    += pps[r] * (unsigned)n_slots;
        end[r]  = cum;
        base[r] = off;
        off    += region_bytes;
    }

    static bool attr_done = false;
    if (!attr_done) {
        cudaFuncSetAttribute(tma_gather_copy,
                             cudaFuncAttributeMaxDynamicSharedMemorySize,
                             SM_TOTAL);
        attr_done = true;
    }

    int blocks = 152 * 2;   // 2 blocks/SM (100KB smem each), one wave
    tma_gather_copy<<<blocks, TPB, SM_TOTAL>>>(
        s[0], c[0], s[1], c[1], s[2], c[2], s[3], c[3],
        (char*)d_out, expert_ids, slot_ids, n_pairs, n_slots,
        per[0], per[1], per[2], per[3],
        pps[0], pps[1], pps[2], pps[3],
        end[0], end[1], end[2], end[3],
        base[0], base[1], base[2], base[3]);
}